// round 8
// baseline (speedup 1.0000x reference)
#include <cuda_runtime.h>

#define BB     2048
#define NCTX   64
#define ZD     64
#define RD     128
#define HD     128
#define NSTEPS 20
#define DT     0.05f
#define DIFF   0.3162277660168379f   /* sqrt(2*dt) */

typedef unsigned long long u64;

// scratch (device globals: no allocations allowed)
__device__ float g_r[BB * RD];      // encoder output r
__device__ float g_grad[BB * ZD];   // clipped energy gradient per step

__device__ __forceinline__ float sigf(float x) { return 1.0f / (1.0f + __expf(-x)); }

__device__ __forceinline__ u64 pk2(float x, float y) {
    u64 r; asm("mov.b64 %0, {%1, %2};" : "=l"(r) : "f"(x), "f"(y)); return r;
}
__device__ __forceinline__ void up2(u64 v, float& x, float& y) {
    asm("mov.b64 {%0, %1}, %2;" : "=f"(x), "=f"(y) : "l"(v));
}
__device__ __forceinline__ void fma2(u64& d, u64 a, u64 b) {
    asm("fma.rn.f32x2 %0, %1, %2, %0;" : "+l"(d) : "l"(a), "l"(b));
}
__device__ __forceinline__ void gbar(int id) {
    asm volatile("bar.sync %0, 128;" :: "r"(id) : "memory");
}

// ---------------------------------------------------------------------------
// Encoder (runs once): r[b] = masked-mean over n of 3-layer set MLP.
// ---------------------------------------------------------------------------
__global__ void __launch_bounds__(128, 1) encoder_kernel(
    const float* __restrict__ x_ctx, const float* __restrict__ y_ctx,
    const float* __restrict__ mask,
    const float* __restrict__ We1, const float* __restrict__ be1,
    const float* __restrict__ We2, const float* __restrict__ be2,
    const float* __restrict__ We3, const float* __restrict__ be3)
{
    extern __shared__ float sm[];
    float4* h1s  = (float4*)sm;           // 128 float4
    float4* h2s  = h1s + 128;             // 128 float4
    float*  We2s = (float*)(h2s + 128);   // 128*128
    float*  We3s = We2s + HD * HD;        // 128*128
    float*  xs   = We3s + HD * HD;        // 128
    float*  ys   = xs + 128;              // 64
    float*  ms   = ys + 64;               // 64

    const int tid = threadIdx.x;
    for (int i = tid; i < HD * HD; i += 128) { We2s[i] = We2[i]; We3s[i] = We3[i]; }
    const float w10 = We1[tid], w11 = We1[HD + tid], w12 = We1[2 * HD + tid];
    const float b1 = be1[tid], b2 = be2[tid], b3 = be3[tid];
    __syncthreads();

    for (int b = blockIdx.x; b < BB; b += gridDim.x) {
        xs[tid] = x_ctx[b * (NCTX * 2) + tid];
        if (tid < NCTX) { ys[tid] = y_ctx[b * NCTX + tid]; ms[tid] = mask[b * NCTX + tid]; }
        __syncthreads();

        float racc = 0.0f;
        #pragma unroll 1
        for (int it = 0; it < NCTX / 4; ++it) {
            const int n0 = it * 4;
            float4 h1;
            float* hp = (float*)&h1;
            #pragma unroll
            for (int q = 0; q < 4; ++q) {
                const int n = n0 + q;
                float p = b1 + xs[2 * n] * w10 + xs[2 * n + 1] * w11 + ys[n] * w12;
                hp[q] = p * sigf(p);
            }
            h1s[tid] = h1;
            __syncthreads();

            float a0 = b2, a1 = b2, a2 = b2, a3 = b2;
            #pragma unroll 8
            for (int k = 0; k < HD; ++k) {
                float4 hh = h1s[k];
                float  w  = We2s[k * HD + tid];
                a0 = fmaf(hh.x, w, a0); a1 = fmaf(hh.y, w, a1);
                a2 = fmaf(hh.z, w, a2); a3 = fmaf(hh.w, w, a3);
            }
            float4 h2;
            h2.x = a0 * sigf(a0); h2.y = a1 * sigf(a1);
            h2.z = a2 * sigf(a2); h2.w = a3 * sigf(a3);
            h2s[tid] = h2;
            __syncthreads();

            a0 = b3; a1 = b3; a2 = b3; a3 = b3;
            #pragma unroll 8
            for (int k = 0; k < HD; ++k) {
                float4 hh = h2s[k];
                float  w  = We3s[k * HD + tid];
                a0 = fmaf(hh.x, w, a0); a1 = fmaf(hh.y, w, a1);
                a2 = fmaf(hh.z, w, a2); a3 = fmaf(hh.w, w, a3);
            }
            racc = fmaf(a0, ms[n0 + 0], racc);
            racc = fmaf(a1, ms[n0 + 1], racc);
            racc = fmaf(a2, ms[n0 + 2], racc);
            racc = fmaf(a3, ms[n0 + 3], racc);
        }
        float msum = 0.0f;
        #pragma unroll
        for (int n = 0; n < NCTX; ++n) msum += ms[n];
        g_r[b * RD + tid] = racc / fmaxf(msum, 1e-6f);
        __syncthreads();
    }
}

// ---------------------------------------------------------------------------
// Energy-gradient kernel. 512 threads = 4 independent 128-thread groups
// sharing ONE SMEM weight copy (named barriers). 16 ctx points per inner
// iteration, f32x2 packed FMA accumulation. Stride-129 weight padding keeps
// both W (fwd) and W^T (bwd) accesses conflict-free. Group scratch base is
// padded to a 16-byte boundary (float4 stores!).
// ---------------------------------------------------------------------------
#define GPB   4            /* groups per block            */
#define GSZ   3072         /* floats of SMEM per group (16B multiple) */
#define WPAD  2            /* pad so gbase is 16B aligned: 25026+2 = 25028 */

__global__ void __launch_bounds__(512, 1) grad_kernel(
    const float* __restrict__ z, const float* __restrict__ x_ctx,
    const float* __restrict__ y_ctx, const float* __restrict__ mask,
    const float* __restrict__ Wd1, const float* __restrict__ bd1,
    const float* __restrict__ Wd2, const float* __restrict__ bd2,
    const float* __restrict__ Wd3, const float* __restrict__ bd3,
    float t)
{
    extern __shared__ float sm[];
    float* Wd1p = sm;                     // 66*129  = 8514
    float* Wd2p = Wd1p + 66 * 129;        // 128*129 = 16512
    float* gbase = Wd2p + 128 * 129 + WPAD; // 16B-aligned

    const int tidb = threadIdx.x;
    const int grp  = tidb >> 7;
    const int tid  = tidb & 127;
    const int bar  = grp + 1;

    float*  gb   = gbase + grp * GSZ;
    float4* h1s  = (float4*)gb;           // 128 rows * 5 float4 (pad) = 2560 f
    float*  wsum = gb + 2560;             // 4 warps * 16 = 64
    float*  xs   = wsum + 64;             // 128
    float*  ys   = xs + 128;              // 64
    float*  ms   = ys + 64;               // 64
    float*  zsh  = ms + 64;               // 64
    float*  ds   = zsh + 64;              // 128

    for (int i = tidb; i < 66 * HD; i += 512) {
        int r = i >> 7, c = i & 127;
        Wd1p[r * 129 + c] = Wd1[i];
    }
    for (int i = tidb; i < HD * HD; i += 512) {
        int r = i >> 7, c = i & 127;
        Wd2p[r * 129 + c] = Wd2[i];
    }
    const float b1 = bd1[tid], b2 = bd2[tid], w3 = Wd3[tid], bd3v = bd3[0];
    __syncthreads();
    const float wx0 = Wd1p[64 * 129 + tid];
    const float wx1 = Wd1p[65 * 129 + tid];
    const int   warp = tid >> 5;

    for (int b = blockIdx.x * GPB + grp; b < BB; b += gridDim.x * GPB) {
        if (tid < ZD) zsh[tid] = z[b * ZD + tid];
        xs[tid] = x_ctx[b * (NCTX * 2) + tid];
        if (tid < NCTX) { ys[tid] = y_ctx[b * NCTX + tid]; ms[tid] = mask[b * NCTX + tid]; }
        gbar(bar);

        float pre1b = b1;
        #pragma unroll 8
        for (int k = 0; k < ZD; ++k) pre1b = fmaf(zsh[k], Wd1p[k * 129 + tid], pre1b);

        float dpsum = 0.0f;
        if (t > 0.0f) {
            #pragma unroll 1
            for (int it = 0; it < NCTX / 16; ++it) {
                const int n0 = it * 16;
                float sd1[16];
                float4 h1v[4];
                float* hp = (float*)h1v;
                #pragma unroll
                for (int q = 0; q < 16; ++q) {
                    const int n = n0 + q;
                    float p = fmaf(xs[2 * n], wx0, fmaf(xs[2 * n + 1], wx1, pre1b));
                    float s = sigf(p);
                    hp[q]  = p * s;
                    sd1[q] = s * (1.0f + p * (1.0f - s));
                }
                #pragma unroll
                for (int c = 0; c < 4; ++c) h1s[tid * 5 + c] = h1v[c];
                gbar(bar);                                    // A

                u64 acc[8];
                const u64 bb2 = pk2(b2, b2);
                #pragma unroll
                for (int i = 0; i < 8; ++i) acc[i] = bb2;
                #pragma unroll 4
                for (int k = 0; k < HD; ++k) {
                    const float w  = Wd2p[k * 129 + tid];
                    const u64   w2 = pk2(w, w);
                    const float4 A0 = h1s[k * 5 + 0];
                    const float4 A1 = h1s[k * 5 + 1];
                    const float4 A2 = h1s[k * 5 + 2];
                    const float4 A3 = h1s[k * 5 + 3];
                    fma2(acc[0], w2, pk2(A0.x, A0.y)); fma2(acc[1], w2, pk2(A0.z, A0.w));
                    fma2(acc[2], w2, pk2(A1.x, A1.y)); fma2(acc[3], w2, pk2(A1.z, A1.w));
                    fma2(acc[4], w2, pk2(A2.x, A2.y)); fma2(acc[5], w2, pk2(A2.z, A2.w));
                    fma2(acc[6], w2, pk2(A3.x, A3.y)); fma2(acc[7], w2, pk2(A3.z, A3.w));
                }
                float a[16];
                #pragma unroll
                for (int i = 0; i < 8; ++i) up2(acc[i], a[2 * i], a[2 * i + 1]);

                float part[16], tder[16];
                #pragma unroll
                for (int q = 0; q < 16; ++q) {
                    const float s = sigf(a[q]);
                    part[q] = a[q] * s * w3;
                    tder[q] = s * (1.0f + a[q] * (1.0f - s));
                }
                #pragma unroll
                for (int off = 16; off; off >>= 1) {
                    #pragma unroll
                    for (int q = 0; q < 16; ++q)
                        part[q] += __shfl_xor_sync(0xffffffffu, part[q], off);
                }
                if ((tid & 31) == 0) {
                    float4* w4 = (float4*)wsum;
                    #pragma unroll
                    for (int c = 0; c < 4; ++c)
                        w4[warp * 4 + c] = make_float4(part[4 * c], part[4 * c + 1],
                                                       part[4 * c + 2], part[4 * c + 3]);
                }
                gbar(bar);                                    // B

                float out[16];
                {
                    const float4* w4 = (const float4*)wsum;
                    #pragma unroll
                    for (int c = 0; c < 4; ++c) {
                        float4 s0 = w4[c], s1 = w4[4 + c], s2 = w4[8 + c], s3 = w4[12 + c];
                        out[4 * c + 0] = s0.x + s1.x + s2.x + s3.x + bd3v;
                        out[4 * c + 1] = s0.y + s1.y + s2.y + s3.y + bd3v;
                        out[4 * c + 2] = s0.z + s1.z + s2.z + s3.z + bd3v;
                        out[4 * c + 3] = s0.w + s1.w + s2.w + s3.w + bd3v;
                    }
                }
                float4 dpv[4];
                float* dpp = (float*)dpv;
                #pragma unroll
                for (int q = 0; q < 16; ++q) {
                    const int n = n0 + q;
                    dpp[q] = -t * (ys[n] - out[q]) * ms[n] * w3 * tder[q];
                }
                #pragma unroll
                for (int c = 0; c < 4; ++c) h1s[tid * 5 + c] = dpv[c];   // reuse buf
                gbar(bar);                                    // C

                u64 cac[8];
                #pragma unroll
                for (int i = 0; i < 8; ++i) cac[i] = 0ull;
                #pragma unroll 4
                for (int k = 0; k < HD; ++k) {
                    const float w  = Wd2p[tid * 129 + k];     // W2^T, conflict-free
                    const u64   w2 = pk2(w, w);
                    const float4 D0 = h1s[k * 5 + 0];
                    const float4 D1 = h1s[k * 5 + 1];
                    const float4 D2 = h1s[k * 5 + 2];
                    const float4 D3 = h1s[k * 5 + 3];
                    fma2(cac[0], w2, pk2(D0.x, D0.y)); fma2(cac[1], w2, pk2(D0.z, D0.w));
                    fma2(cac[2], w2, pk2(D1.x, D1.y)); fma2(cac[3], w2, pk2(D1.z, D1.w));
                    fma2(cac[4], w2, pk2(D2.x, D2.y)); fma2(cac[5], w2, pk2(D2.z, D2.w));
                    fma2(cac[6], w2, pk2(D3.x, D3.y)); fma2(cac[7], w2, pk2(D3.z, D3.w));
                }
                #pragma unroll
                for (int i = 0; i < 8; ++i) {
                    float c0, c1;
                    up2(cac[i], c0, c1);
                    dpsum = fmaf(c0, sd1[2 * i], dpsum);
                    dpsum = fmaf(c1, sd1[2 * i + 1], dpsum);
                }
                gbar(bar);                                    // D (h1s reuse next iter)
            }
        }
        ds[tid] = dpsum;
        gbar(bar);
        if (tid < ZD) {
            float acc = 0.0f;
            #pragma unroll 8
            for (int j = 0; j < HD; ++j) acc = fmaf(ds[j], Wd1p[tid * 129 + j], acc);
            float g = zsh[tid] + acc;
            g = fminf(fmaxf(g, -100.0f), 100.0f);
            g_grad[b * ZD + tid] = g;
        }
        gbar(bar);
    }
}

// ---------------------------------------------------------------------------
// Drift + z update, 4 batch elements per iteration (float4 broadcasts).
// ---------------------------------------------------------------------------
__global__ void __launch_bounds__(128, 1) drift_kernel(
    float* __restrict__ z, const float* __restrict__ noise,
    const float* __restrict__ Wf1, const float* __restrict__ bf1,
    const float* __restrict__ Wf2, const float* __restrict__ bf2,
    const float* __restrict__ Wf3, const float* __restrict__ bf3,
    float t)
{
    extern __shared__ float sm[];
    float*  Wf1s = sm;                       // 193*128 = 24704
    float*  Wf2s = Wf1s + 193 * HD;          // 16384
    float*  Wf3s = Wf2s + HD * HD;           // 8192
    float4* f1sT = (float4*)(Wf3s + HD * ZD); // 128 f4 (offset 49280 f, 16B ok)
    float4* f2sT = f1sT + 128;               // 128 f4
    float4* zshT = f2sT + 128;               // 64 f4
    float4* rshT = zshT + 64;                // 128 f4

    const int tid = threadIdx.x;
    for (int i = tid; i < 193 * HD; i += 128) Wf1s[i] = Wf1[i];
    for (int i = tid; i < HD * HD; i += 128)  Wf2s[i] = Wf2[i];
    for (int i = tid; i < HD * ZD; i += 128)  Wf3s[i] = Wf3[i];
    const float b1 = bf1[tid], b2 = bf2[tid];
    const float bf3v = bf3[tid & 63];
    __syncthreads();
    const float wt = Wf1s[192 * HD + tid];
    const int kk = tid & 63, g2 = tid >> 6;

    for (int b0 = blockIdx.x * 4; b0 < BB; b0 += gridDim.x * 4) {
        float* zf = (float*)zshT;
        float* rf = (float*)rshT;
        #pragma unroll
        for (int i = tid; i < 4 * ZD; i += 128) {
            int q = i >> 6, k = i & 63;
            zf[k * 4 + q] = z[(b0 + q) * ZD + k];
        }
        #pragma unroll
        for (int i = tid; i < 4 * RD; i += 128) {
            int q = i >> 7, k = i & 127;
            rf[k * 4 + q] = g_r[(b0 + q) * RD + k];
        }
        __syncthreads();

        const float pb = fmaf(t, wt, b1);
        float p0 = pb, p1 = pb, p2 = pb, p3 = pb;
        #pragma unroll 8
        for (int k = 0; k < ZD; ++k) {
            const float w = Wf1s[k * HD + tid];
            const float4 v = zshT[k];
            p0 = fmaf(v.x, w, p0); p1 = fmaf(v.y, w, p1);
            p2 = fmaf(v.z, w, p2); p3 = fmaf(v.w, w, p3);
        }
        #pragma unroll 8
        for (int k = 0; k < RD; ++k) {
            const float w = Wf1s[(ZD + k) * HD + tid];
            const float4 v = rshT[k];
            p0 = fmaf(v.x, w, p0); p1 = fmaf(v.y, w, p1);
            p2 = fmaf(v.z, w, p2); p3 = fmaf(v.w, w, p3);
        }
        f1sT[tid] = make_float4(p0 * sigf(p0), p1 * sigf(p1), p2 * sigf(p2), p3 * sigf(p3));
        __syncthreads();

        p0 = b2; p1 = b2; p2 = b2; p3 = b2;
        #pragma unroll 8
        for (int k = 0; k < HD; ++k) {
            const float w = Wf2s[k * HD + tid];
            const float4 v = f1sT[k];
            p0 = fmaf(v.x, w, p0); p1 = fmaf(v.y, w, p1);
            p2 = fmaf(v.z, w, p2); p3 = fmaf(v.w, w, p3);
        }
        f2sT[tid] = make_float4(p0 * sigf(p0), p1 * sigf(p1), p2 * sigf(p2), p3 * sigf(p3));
        __syncthreads();

        // layer 3: thread covers (kk, q=g2) and (kk, q=g2+2)
        float accA = 0.0f, accB = 0.0f;
        #pragma unroll 8
        for (int j = 0; j < HD; ++j) {
            const float w = Wf3s[j * ZD + kk];
            const float4 v = f2sT[j];
            const float vA = g2 ? v.y : v.x;
            const float vB = g2 ? v.w : v.z;
            accA = fmaf(vA, w, accA);
            accB = fmaf(vB, w, accB);
        }
        {
            const int qA = g2, qB = g2 + 2;
            const int bA = b0 + qA, bB = b0 + qB;
            const float znA = zf[kk * 4 + qA]
                + (bf3v + accA - g_grad[bA * ZD + kk]) * DT
                + DIFF * noise[bA * ZD + kk];
            const float znB = zf[kk * 4 + qB]
                + (bf3v + accB - g_grad[bB * ZD + kk]) * DT
                + DIFF * noise[bB * ZD + kk];
            z[bA * ZD + kk] = znA;
            z[bB * ZD + kk] = znB;
        }
        __syncthreads();
    }
}

// ---------------------------------------------------------------------------
extern "C" void kernel_launch(void* const* d_in, const int* in_sizes, int n_in,
                              void* d_out, int out_size)
{
    const float* x_ctx  = (const float*)d_in[0];
    const float* y_ctx  = (const float*)d_in[1];
    const float* mask   = (const float*)d_in[2];
    const float* z0     = (const float*)d_in[3];
    const float* noises = (const float*)d_in[4];
    const float* We1 = (const float*)d_in[5];  const float* be1 = (const float*)d_in[6];
    const float* We2 = (const float*)d_in[7];  const float* be2 = (const float*)d_in[8];
    const float* We3 = (const float*)d_in[9];  const float* be3 = (const float*)d_in[10];
    const float* Wd1 = (const float*)d_in[11]; const float* bd1 = (const float*)d_in[12];
    const float* Wd2 = (const float*)d_in[13]; const float* bd2 = (const float*)d_in[14];
    const float* Wd3 = (const float*)d_in[15]; const float* bd3 = (const float*)d_in[16];
    const float* Wf1 = (const float*)d_in[17]; const float* bf1 = (const float*)d_in[18];
    const float* Wf2 = (const float*)d_in[19]; const float* bf2 = (const float*)d_in[20];
    const float* Wf3 = (const float*)d_in[21]; const float* bf3 = (const float*)d_in[22];
    float* z = (float*)d_out;   // z buffer lives in d_out; final state is the answer

    const size_t smE = (size_t)(512 + 512 + 16384 + 16384 + 128 + 64 + 64) * 4;
    const size_t smG = (size_t)(66 * 129 + 128 * 129 + WPAD + GPB * GSZ) * 4;
    const size_t smF = (size_t)(193 * 128 + 128 * 128 + 128 * 64
                                + 512 + 512 + 256 + 512) * 4;

    cudaFuncSetAttribute(encoder_kernel, cudaFuncAttributeMaxDynamicSharedMemorySize, (int)smE);
    cudaFuncSetAttribute(grad_kernel,    cudaFuncAttributeMaxDynamicSharedMemorySize, (int)smG);
    cudaFuncSetAttribute(drift_kernel,   cudaFuncAttributeMaxDynamicSharedMemorySize, (int)smF);

    cudaMemcpyAsync(z, z0, (size_t)BB * ZD * sizeof(float), cudaMemcpyDeviceToDevice);
    encoder_kernel<<<148, 128, smE>>>(x_ctx, y_ctx, mask, We1, be1, We2, be2, We3, be3);

    for (int s = 0; s < NSTEPS; ++s) {
        const float t = (float)s * DT;
        grad_kernel<<<148, 512, smG>>>(z, x_ctx, y_ctx, mask,
                                       Wd1, bd1, Wd2, bd2, Wd3, bd3, t);
        drift_kernel<<<148, 128, smF>>>(z, noises + (size_t)s * BB * ZD,
                                        Wf1, bf1, Wf2, bf2, Wf3, bf3, t);
    }
}

// round 12
// speedup vs baseline: 1.2615x; 1.2615x over previous
#include <cuda_runtime.h>

#define BB     2048
#define NCTX   64
#define ZD     64
#define RD     128
#define HD     128
#define NSTEPS 20
#define DT     0.05f
#define DIFF   0.3162277660168379f

typedef unsigned long long u64;

__device__ float g_r[BB * RD];
__device__ float g_grad[BB * ZD];

__device__ __forceinline__ float sigf(float x) { return 1.0f / (1.0f + __expf(-x)); }
__device__ __forceinline__ u64 pk2(float x, float y) {
    u64 r; asm("mov.b64 %0, {%1, %2};" : "=l"(r) : "f"(x), "f"(y)); return r;
}
__device__ __forceinline__ void up2(u64 v, float& x, float& y) {
    asm("mov.b64 {%0, %1}, %2;" : "=f"(x), "=f"(y) : "l"(v));
}
__device__ __forceinline__ void fma2(u64& d, u64 a, u64 b) {
    asm("fma.rn.f32x2 %0, %1, %2, %0;" : "+l"(d) : "l"(a), "l"(b));
}
__device__ __forceinline__ void gbar64(int id) {
    asm volatile("bar.sync %0, 64;" :: "r"(id) : "memory");
}

// ---------------- Encoder (unchanged, runs once) ----------------
__global__ void __launch_bounds__(128, 1) encoder_kernel(
    const float* __restrict__ x_ctx, const float* __restrict__ y_ctx,
    const float* __restrict__ mask,
    const float* __restrict__ We1, const float* __restrict__ be1,
    const float* __restrict__ We2, const float* __restrict__ be2,
    const float* __restrict__ We3, const float* __restrict__ be3)
{
    extern __shared__ float sm[];
    float4* h1s  = (float4*)sm;
    float4* h2s  = h1s + 128;
    float*  We2s = (float*)(h2s + 128);
    float*  We3s = We2s + HD * HD;
    float*  xs   = We3s + HD * HD;
    float*  ys   = xs + 128;
    float*  ms   = ys + 64;

    const int tid = threadIdx.x;
    for (int i = tid; i < HD * HD; i += 128) { We2s[i] = We2[i]; We3s[i] = We3[i]; }
    const float w10 = We1[tid], w11 = We1[HD + tid], w12 = We1[2 * HD + tid];
    const float b1 = be1[tid], b2 = be2[tid], b3 = be3[tid];
    __syncthreads();

    for (int b = blockIdx.x; b < BB; b += gridDim.x) {
        xs[tid] = x_ctx[b * (NCTX * 2) + tid];
        if (tid < NCTX) { ys[tid] = y_ctx[b * NCTX + tid]; ms[tid] = mask[b * NCTX + tid]; }
        __syncthreads();

        float racc = 0.0f;
        #pragma unroll 1
        for (int it = 0; it < NCTX / 4; ++it) {
            const int n0 = it * 4;
            float4 h1;
            float* hp = (float*)&h1;
            #pragma unroll
            for (int q = 0; q < 4; ++q) {
                const int n = n0 + q;
                float p = b1 + xs[2 * n] * w10 + xs[2 * n + 1] * w11 + ys[n] * w12;
                hp[q] = p * sigf(p);
            }
            h1s[tid] = h1;
            __syncthreads();

            float a0 = b2, a1 = b2, a2 = b2, a3 = b2;
            #pragma unroll 8
            for (int k = 0; k < HD; ++k) {
                float4 hh = h1s[k];
                float  w  = We2s[k * HD + tid];
                a0 = fmaf(hh.x, w, a0); a1 = fmaf(hh.y, w, a1);
                a2 = fmaf(hh.z, w, a2); a3 = fmaf(hh.w, w, a3);
            }
            float4 h2;
            h2.x = a0 * sigf(a0); h2.y = a1 * sigf(a1);
            h2.z = a2 * sigf(a2); h2.w = a3 * sigf(a3);
            h2s[tid] = h2;
            __syncthreads();

            a0 = b3; a1 = b3; a2 = b3; a3 = b3;
            #pragma unroll 8
            for (int k = 0; k < HD; ++k) {
                float4 hh = h2s[k];
                float  w  = We3s[k * HD + tid];
                a0 = fmaf(hh.x, w, a0); a1 = fmaf(hh.y, w, a1);
                a2 = fmaf(hh.z, w, a2); a3 = fmaf(hh.w, w, a3);
            }
            racc = fmaf(a0, ms[n0 + 0], racc);
            racc = fmaf(a1, ms[n0 + 1], racc);
            racc = fmaf(a2, ms[n0 + 2], racc);
            racc = fmaf(a3, ms[n0 + 3], racc);
        }
        float msum = 0.0f;
        #pragma unroll
        for (int n = 0; n < NCTX; ++n) msum += ms[n];
        g_r[b * RD + tid] = racc / fmaxf(msum, 1e-6f);
        __syncthreads();
    }
}

// ---------------- Grad kernel: 8 groups x 64 threads, 2 cols/thread ----------------
#define GPB   8
#define GSZ   1488
#define WPAD  2

__global__ void __launch_bounds__(512, 1) grad_kernel(
    const float* __restrict__ z, const float* __restrict__ x_ctx,
    const float* __restrict__ y_ctx, const float* __restrict__ mask,
    const float* __restrict__ Wd1, const float* __restrict__ bd1,
    const float* __restrict__ Wd2, const float* __restrict__ bd2,
    const float* __restrict__ Wd3, const float* __restrict__ bd3,
    float t)
{
    extern __shared__ float sm[];
    float* Wd1p  = sm;                       // 66*129
    float* Wd2p  = Wd1p + 66 * 129;          // 128*129
    float* gbase = Wd2p + 128 * 129 + WPAD;  // 16B aligned

    const int tidb = threadIdx.x;
    const int grp  = tidb >> 6;
    const int tid  = tidb & 63;
    const int bar  = grp + 1;
    const int c0   = tid, c1 = tid + 64;
    const int warp = tid >> 5;
    const int lane = tid & 31;

    float* gb   = gbase + grp * GSZ;
    float* h1T  = gb;            // 128 cols x 8 ctx
    float* wsum = gb + 1024;     // 2 warps x 8
    float* xs   = gb + 1040;     // 128
    float* ys   = gb + 1168;     // 64
    float* ms   = gb + 1232;     // 64
    float* zsh  = gb + 1296;     // 64
    float* ds   = gb + 1360;     // 128

    for (int i = tidb; i < 66 * HD; i += 512) {
        int r = i >> 7, c = i & 127;
        Wd1p[r * 129 + c] = Wd1[i];
    }
    for (int i = tidb; i < HD * HD; i += 512) {
        int r = i >> 7, c = i & 127;
        Wd2p[r * 129 + c] = Wd2[i];
    }
    const float b1a = bd1[c0], b1b = bd1[c1];
    const float b2a = bd2[c0], b2b = bd2[c1];
    const float w3a = Wd3[c0], w3b = Wd3[c1], bd3v = bd3[0];
    __syncthreads();
    const float wx0a = Wd1p[64 * 129 + c0], wx1a = Wd1p[65 * 129 + c0];
    const float wx0b = Wd1p[64 * 129 + c1], wx1b = Wd1p[65 * 129 + c1];

    for (int b = blockIdx.x * GPB + grp; b < BB; b += gridDim.x * GPB) {
        zsh[tid] = z[b * ZD + tid];
        xs[tid]      = x_ctx[b * (NCTX * 2) + tid];
        xs[tid + 64] = x_ctx[b * (NCTX * 2) + tid + 64];
        ys[tid] = y_ctx[b * NCTX + tid];
        ms[tid] = mask[b * NCTX + tid];
        gbar64(bar);

        float pre1a = b1a, pre1b = b1b;
        #pragma unroll 8
        for (int k = 0; k < ZD; ++k) {
            const float zk = zsh[k];
            pre1a = fmaf(zk, Wd1p[k * 129 + c0], pre1a);
            pre1b = fmaf(zk, Wd1p[k * 129 + c1], pre1b);
        }

        float dps0 = 0.0f, dps1 = 0.0f;
        if (t > 0.0f) {
            #pragma unroll 1
            for (int it = 0; it < NCTX / 8; ++it) {
                const int n0 = it * 8;
                float ha[8], hb[8], sda[8], sdb[8];
                #pragma unroll
                for (int q = 0; q < 8; ++q) {
                    const int n = n0 + q;
                    const float xa = xs[2 * n], xb = xs[2 * n + 1];
                    float p = fmaf(xa, wx0a, fmaf(xb, wx1a, pre1a));
                    float s = sigf(p);
                    ha[q] = p * s; sda[q] = s * (1.0f + p * (1.0f - s));
                    p = fmaf(xa, wx0b, fmaf(xb, wx1b, pre1b));
                    s = sigf(p);
                    hb[q] = p * s; sdb[q] = s * (1.0f + p * (1.0f - s));
                }
                *(float4*)&h1T[c0 * 8]     = make_float4(ha[0], ha[1], ha[2], ha[3]);
                *(float4*)&h1T[c0 * 8 + 4] = make_float4(ha[4], ha[5], ha[6], ha[7]);
                *(float4*)&h1T[c1 * 8]     = make_float4(hb[0], hb[1], hb[2], hb[3]);
                *(float4*)&h1T[c1 * 8 + 4] = make_float4(hb[4], hb[5], hb[6], hb[7]);
                gbar64(bar);                                  // A

                u64 ac0[4], ac1[4];
                #pragma unroll
                for (int p = 0; p < 4; ++p) { ac0[p] = pk2(b2a, b2a); ac1[p] = pk2(b2b, b2b); }
                #pragma unroll 4
                for (int k = 0; k < HD; ++k) {
                    const float w0 = Wd2p[k * 129 + c0];
                    const float w1 = Wd2p[k * 129 + c1];
                    const float4 HA = *(const float4*)&h1T[k * 8];
                    const float4 HB = *(const float4*)&h1T[k * 8 + 4];
                    const u64 h0 = pk2(HA.x, HA.y), h1p = pk2(HA.z, HA.w);
                    const u64 h2p = pk2(HB.x, HB.y), h3p = pk2(HB.z, HB.w);
                    u64 wd = pk2(w0, w0);
                    fma2(ac0[0], wd, h0); fma2(ac0[1], wd, h1p);
                    fma2(ac0[2], wd, h2p); fma2(ac0[3], wd, h3p);
                    wd = pk2(w1, w1);
                    fma2(ac1[0], wd, h0); fma2(ac1[1], wd, h1p);
                    fma2(ac1[2], wd, h2p); fma2(ac1[3], wd, h3p);
                }
                float aa[8], ab[8];
                #pragma unroll
                for (int p = 0; p < 4; ++p) {
                    up2(ac0[p], aa[2 * p], aa[2 * p + 1]);
                    up2(ac1[p], ab[2 * p], ab[2 * p + 1]);
                }
                float ta[8], tb[8], part[8];
                #pragma unroll
                for (int q = 0; q < 8; ++q) {
                    float s = sigf(aa[q]);
                    part[q] = aa[q] * s * w3a;
                    ta[q] = s * (1.0f + aa[q] * (1.0f - s));
                    s = sigf(ab[q]);
                    part[q] = fmaf(ab[q] * s, w3b, part[q]);
                    tb[q] = s * (1.0f + ab[q] * (1.0f - s));
                }
                #pragma unroll
                for (int off = 16; off; off >>= 1) {
                    #pragma unroll
                    for (int q = 0; q < 8; ++q)
                        part[q] += __shfl_xor_sync(0xffffffffu, part[q], off);
                }
                if (lane == 0) {
                    *(float4*)&wsum[warp * 8]     = make_float4(part[0], part[1], part[2], part[3]);
                    *(float4*)&wsum[warp * 8 + 4] = make_float4(part[4], part[5], part[6], part[7]);
                }
                gbar64(bar);                                  // B

                float da[8], db[8];
                #pragma unroll
                for (int q = 0; q < 8; ++q) {
                    const int n = n0 + q;
                    const float out = wsum[q] + wsum[8 + q] + bd3v;
                    const float e = -t * (ys[n] - out) * ms[n];
                    da[q] = e * w3a * ta[q];
                    db[q] = e * w3b * tb[q];
                }
                *(float4*)&h1T[c0 * 8]     = make_float4(da[0], da[1], da[2], da[3]);
                *(float4*)&h1T[c0 * 8 + 4] = make_float4(da[4], da[5], da[6], da[7]);
                *(float4*)&h1T[c1 * 8]     = make_float4(db[0], db[1], db[2], db[3]);
                *(float4*)&h1T[c1 * 8 + 4] = make_float4(db[4], db[5], db[6], db[7]);
                gbar64(bar);                                  // C

                u64 bc0[4], bc1[4];
                #pragma unroll
                for (int p = 0; p < 4; ++p) { bc0[p] = 0ull; bc1[p] = 0ull; }
                #pragma unroll 4
                for (int k = 0; k < HD; ++k) {
                    const float w0 = Wd2p[c0 * 129 + k];      // W2^T rows
                    const float w1 = Wd2p[c1 * 129 + k];
                    const float4 DA = *(const float4*)&h1T[k * 8];
                    const float4 DB = *(const float4*)&h1T[k * 8 + 4];
                    const u64 d0 = pk2(DA.x, DA.y), d1 = pk2(DA.z, DA.w);
                    const u64 d2 = pk2(DB.x, DB.y), d3 = pk2(DB.z, DB.w);
                    u64 wd = pk2(w0, w0);
                    fma2(bc0[0], wd, d0); fma2(bc0[1], wd, d1);
                    fma2(bc0[2], wd, d2); fma2(bc0[3], wd, d3);
                    wd = pk2(w1, w1);
                    fma2(bc1[0], wd, d0); fma2(bc1[1], wd, d1);
                    fma2(bc1[2], wd, d2); fma2(bc1[3], wd, d3);
                }
                #pragma unroll
                for (int p = 0; p < 4; ++p) {
                    float u, v;
                    up2(bc0[p], u, v);
                    dps0 = fmaf(u, sda[2 * p], dps0);
                    dps0 = fmaf(v, sda[2 * p + 1], dps0);
                    up2(bc1[p], u, v);
                    dps1 = fmaf(u, sdb[2 * p], dps1);
                    dps1 = fmaf(v, sdb[2 * p + 1], dps1);
                }
                gbar64(bar);                                  // D
            }
        }
        ds[c0] = dps0;
        ds[c1] = dps1;
        gbar64(bar);
        {
            float acc = 0.0f;
            #pragma unroll 8
            for (int j = 0; j < HD; ++j) acc = fmaf(ds[j], Wd1p[tid * 129 + j], acc);
            float g = zsh[tid] + acc;
            g = fminf(fmaxf(g, -100.0f), 100.0f);
            g_grad[b * ZD + tid] = g;
        }
        gbar64(bar);
    }
}

// ---------------- Drift + z update (unchanged from R6) ----------------
__global__ void __launch_bounds__(128, 1) drift_kernel(
    float* __restrict__ z, const float* __restrict__ noise,
    const float* __restrict__ Wf1, const float* __restrict__ bf1,
    const float* __restrict__ Wf2, const float* __restrict__ bf2,
    const float* __restrict__ Wf3, const float* __restrict__ bf3,
    float t)
{
    extern __shared__ float sm[];
    float*  Wf1s = sm;
    float*  Wf2s = Wf1s + 193 * HD;
    float*  Wf3s = Wf2s + HD * HD;
    float4* f1sT = (float4*)(Wf3s + HD * ZD);
    float4* f2sT = f1sT + 128;
    float4* zshT = f2sT + 128;
    float4* rshT = zshT + 64;

    const int tid = threadIdx.x;
    for (int i = tid; i < 193 * HD; i += 128) Wf1s[i] = Wf1[i];
    for (int i = tid; i < HD * HD; i += 128)  Wf2s[i] = Wf2[i];
    for (int i = tid; i < HD * ZD; i += 128)  Wf3s[i] = Wf3[i];
    const float b1 = bf1[tid], b2 = bf2[tid];
    const float bf3v = bf3[tid & 63];
    __syncthreads();
    const float wt = Wf1s[192 * HD + tid];
    const int kk = tid & 63, g2 = tid >> 6;

    for (int b0 = blockIdx.x * 4; b0 < BB; b0 += gridDim.x * 4) {
        float* zf = (float*)zshT;
        float* rf = (float*)rshT;
        #pragma unroll
        for (int i = tid; i < 4 * ZD; i += 128) {
            int q = i >> 6, k = i & 63;
            zf[k * 4 + q] = z[(b0 + q) * ZD + k];
        }
        #pragma unroll
        for (int i = tid; i < 4 * RD; i += 128) {
            int q = i >> 7, k = i & 127;
            rf[k * 4 + q] = g_r[(b0 + q) * RD + k];
        }
        __syncthreads();

        const float pb = fmaf(t, wt, b1);
        float p0 = pb, p1 = pb, p2 = pb, p3 = pb;
        #pragma unroll 8
        for (int k = 0; k < ZD; ++k) {
            const float w = Wf1s[k * HD + tid];
            const float4 v = zshT[k];
            p0 = fmaf(v.x, w, p0); p1 = fmaf(v.y, w, p1);
            p2 = fmaf(v.z, w, p2); p3 = fmaf(v.w, w, p3);
        }
        #pragma unroll 8
        for (int k = 0; k < RD; ++k) {
            const float w = Wf1s[(ZD + k) * HD + tid];
            const float4 v = rshT[k];
            p0 = fmaf(v.x, w, p0); p1 = fmaf(v.y, w, p1);
            p2 = fmaf(v.z, w, p2); p3 = fmaf(v.w, w, p3);
        }
        f1sT[tid] = make_float4(p0 * sigf(p0), p1 * sigf(p1), p2 * sigf(p2), p3 * sigf(p3));
        __syncthreads();

        p0 = b2; p1 = b2; p2 = b2; p3 = b2;
        #pragma unroll 8
        for (int k = 0; k < HD; ++k) {
            const float w = Wf2s[k * HD + tid];
            const float4 v = f1sT[k];
            p0 = fmaf(v.x, w, p0); p1 = fmaf(v.y, w, p1);
            p2 = fmaf(v.z, w, p2); p3 = fmaf(v.w, w, p3);
        }
        f2sT[tid] = make_float4(p0 * sigf(p0), p1 * sigf(p1), p2 * sigf(p2), p3 * sigf(p3));
        __syncthreads();

        float accA = 0.0f, accB = 0.0f;
        #pragma unroll 8
        for (int j = 0; j < HD; ++j) {
            const float w = Wf3s[j * ZD + kk];
            const float4 v = f2sT[j];
            const float vA = g2 ? v.y : v.x;
            const float vB = g2 ? v.w : v.z;
            accA = fmaf(vA, w, accA);
            accB = fmaf(vB, w, accB);
        }
        {
            const int qA = g2, qB = g2 + 2;
            const int bA = b0 + qA, bB = b0 + qB;
            z[bA * ZD + kk] = zf[kk * 4 + qA]
                + (bf3v + accA - g_grad[bA * ZD + kk]) * DT
                + DIFF * noise[bA * ZD + kk];
            z[bB * ZD + kk] = zf[kk * 4 + qB]
                + (bf3v + accB - g_grad[bB * ZD + kk]) * DT
                + DIFF * noise[bB * ZD + kk];
        }
        __syncthreads();
    }
}

// ---------------------------------------------------------------------------
extern "C" void kernel_launch(void* const* d_in, const int* in_sizes, int n_in,
                              void* d_out, int out_size)
{
    const float* x_ctx  = (const float*)d_in[0];
    const float* y_ctx  = (const float*)d_in[1];
    const float* mask   = (const float*)d_in[2];
    const float* z0     = (const float*)d_in[3];
    const float* noises = (const float*)d_in[4];
    const float* We1 = (const float*)d_in[5];  const float* be1 = (const float*)d_in[6];
    const float* We2 = (const float*)d_in[7];  const float* be2 = (const float*)d_in[8];
    const float* We3 = (const float*)d_in[9];  const float* be3 = (const float*)d_in[10];
    const float* Wd1 = (const float*)d_in[11]; const float* bd1 = (const float*)d_in[12];
    const float* Wd2 = (const float*)d_in[13]; const float* bd2 = (const float*)d_in[14];
    const float* Wd3 = (const float*)d_in[15]; const float* bd3 = (const float*)d_in[16];
    const float* Wf1 = (const float*)d_in[17]; const float* bf1 = (const float*)d_in[18];
    const float* Wf2 = (const float*)d_in[19]; const float* bf2 = (const float*)d_in[20];
    const float* Wf3 = (const float*)d_in[21]; const float* bf3 = (const float*)d_in[22];
    float* z = (float*)d_out;

    const size_t smE = (size_t)(512 + 512 + 16384 + 16384 + 128 + 64 + 64) * 4;
    const size_t smG = (size_t)(66 * 129 + 128 * 129 + WPAD + GPB * GSZ) * 4;
    const size_t smF = (size_t)(193 * 128 + 128 * 128 + 128 * 64
                                + 512 + 512 + 256 + 512) * 4;

    cudaFuncSetAttribute(encoder_kernel, cudaFuncAttributeMaxDynamicSharedMemorySize, (int)smE);
    cudaFuncSetAttribute(grad_kernel,    cudaFuncAttributeMaxDynamicSharedMemorySize, (int)smG);
    cudaFuncSetAttribute(drift_kernel,   cudaFuncAttributeMaxDynamicSharedMemorySize, (int)smF);

    cudaMemcpyAsync(z, z0, (size_t)BB * ZD * sizeof(float), cudaMemcpyDeviceToDevice);
    encoder_kernel<<<148, 128, smE>>>(x_ctx, y_ctx, mask, We1, be1, We2, be2, We3, be3);

    for (int s = 0; s < NSTEPS; ++s) {
        const float t = (float)s * DT;
        grad_kernel<<<148, 512, smG>>>(z, x_ctx, y_ctx, mask,
                                       Wd1, bd1, Wd2, bd2, Wd3, bd3, t);
        drift_kernel<<<148, 128, smF>>>(z, noises + (size_t)s * BB * ZD,
                                        Wf1, bf1, Wf2, bf2, Wf3, bf3, t);
    }
}

// round 13
// speedup vs baseline: 1.3952x; 1.1060x over previous
#include <cuda_runtime.h>

#define BB     2048
#define NCTX   64
#define ZD     64
#define RD     128
#define HD     128
#define NSTEPS 20
#define DT     0.05f
#define DIFF   0.3162277660168379f

typedef unsigned long long u64;

__device__ float g_r[BB * RD];
__device__ float g_grad[BB * ZD];

__device__ __forceinline__ float sigf(float x) { return 1.0f / (1.0f + __expf(-x)); }
__device__ __forceinline__ u64 pk2(float x, float y) {
    u64 r; asm("mov.b64 %0, {%1, %2};" : "=l"(r) : "f"(x), "f"(y)); return r;
}
__device__ __forceinline__ void up2(u64 v, float& x, float& y) {
    asm("mov.b64 {%0, %1}, %2;" : "=f"(x), "=f"(y) : "l"(v));
}
__device__ __forceinline__ void fma2(u64& d, u64 a, u64 b) {
    asm("fma.rn.f32x2 %0, %1, %2, %0;" : "+l"(d) : "l"(a), "l"(b));
}

// ---------------- Encoder (unchanged, runs once) ----------------
__global__ void __launch_bounds__(128, 1) encoder_kernel(
    const float* __restrict__ x_ctx, const float* __restrict__ y_ctx,
    const float* __restrict__ mask,
    const float* __restrict__ We1, const float* __restrict__ be1,
    const float* __restrict__ We2, const float* __restrict__ be2,
    const float* __restrict__ We3, const float* __restrict__ be3)
{
    extern __shared__ float sm[];
    float4* h1s  = (float4*)sm;
    float4* h2s  = h1s + 128;
    float*  We2s = (float*)(h2s + 128);
    float*  We3s = We2s + HD * HD;
    float*  xs   = We3s + HD * HD;
    float*  ys   = xs + 128;
    float*  ms   = ys + 64;

    const int tid = threadIdx.x;
    for (int i = tid; i < HD * HD; i += 128) { We2s[i] = We2[i]; We3s[i] = We3[i]; }
    const float w10 = We1[tid], w11 = We1[HD + tid], w12 = We1[2 * HD + tid];
    const float b1 = be1[tid], b2 = be2[tid], b3 = be3[tid];
    __syncthreads();

    for (int b = blockIdx.x; b < BB; b += gridDim.x) {
        xs[tid] = x_ctx[b * (NCTX * 2) + tid];
        if (tid < NCTX) { ys[tid] = y_ctx[b * NCTX + tid]; ms[tid] = mask[b * NCTX + tid]; }
        __syncthreads();

        float racc = 0.0f;
        #pragma unroll 1
        for (int it = 0; it < NCTX / 4; ++it) {
            const int n0 = it * 4;
            float4 h1;
            float* hp = (float*)&h1;
            #pragma unroll
            for (int q = 0; q < 4; ++q) {
                const int n = n0 + q;
                float p = b1 + xs[2 * n] * w10 + xs[2 * n + 1] * w11 + ys[n] * w12;
                hp[q] = p * sigf(p);
            }
            h1s[tid] = h1;
            __syncthreads();

            float a0 = b2, a1 = b2, a2 = b2, a3 = b2;
            #pragma unroll 8
            for (int k = 0; k < HD; ++k) {
                float4 hh = h1s[k];
                float  w  = We2s[k * HD + tid];
                a0 = fmaf(hh.x, w, a0); a1 = fmaf(hh.y, w, a1);
                a2 = fmaf(hh.z, w, a2); a3 = fmaf(hh.w, w, a3);
            }
            float4 h2;
            h2.x = a0 * sigf(a0); h2.y = a1 * sigf(a1);
            h2.z = a2 * sigf(a2); h2.w = a3 * sigf(a3);
            h2s[tid] = h2;
            __syncthreads();

            a0 = b3; a1 = b3; a2 = b3; a3 = b3;
            #pragma unroll 8
            for (int k = 0; k < HD; ++k) {
                float4 hh = h2s[k];
                float  w  = We3s[k * HD + tid];
                a0 = fmaf(hh.x, w, a0); a1 = fmaf(hh.y, w, a1);
                a2 = fmaf(hh.z, w, a2); a3 = fmaf(hh.w, w, a3);
            }
            racc = fmaf(a0, ms[n0 + 0], racc);
            racc = fmaf(a1, ms[n0 + 1], racc);
            racc = fmaf(a2, ms[n0 + 2], racc);
            racc = fmaf(a3, ms[n0 + 3], racc);
        }
        float msum = 0.0f;
        #pragma unroll
        for (int n = 0; n < NCTX; ++n) msum += ms[n];
        g_r[b * RD + tid] = racc / fmaxf(msum, 1e-6f);
        __syncthreads();
    }
}

// ---------------- Grad kernel: 14 warp-groups, 4 cols/lane, warp-sync ----------------
#define GPB   14
#define GSZ   1984   /* h1T 128*12 + xs 128 + ys 64 + ms 64 + zsh 64 + ds 128 */

__global__ void __launch_bounds__(448, 1) grad_kernel(
    const float* __restrict__ z, const float* __restrict__ x_ctx,
    const float* __restrict__ y_ctx, const float* __restrict__ mask,
    const float* __restrict__ Wd1, const float* __restrict__ bd1,
    const float* __restrict__ Wd2, const float* __restrict__ bd2,
    const float* __restrict__ Wd3, const float* __restrict__ bd3,
    float t)
{
    extern __shared__ float sm[];
    float* Wd1p  = sm;                       // 66*129 = 8514
    float* Wd2p  = Wd1p + 66 * 129;          // 128*129 = 16512
    float* gbase = Wd2p + 128 * 129 + 2;     // 25028 floats -> 16B aligned

    const int tidb = threadIdx.x;
    const int grp  = tidb >> 5;
    const int lane = tidb & 31;

    float* gb  = gbase + grp * GSZ;
    float* h1T = gb;             // 128 rows x stride 12 (h1, reused for dpre2)
    float* xs  = gb + 1536;      // 128
    float* ys  = xs + 128;       // 64
    float* ms  = ys + 64;        // 64
    float* zsh = ms + 64;        // 64
    float* ds  = zsh + 64;       // 128

    for (int i = tidb; i < 66 * HD; i += 448) {
        int r = i >> 7, c = i & 127;
        Wd1p[r * 129 + c] = Wd1[i];
    }
    for (int i = tidb; i < HD * HD; i += 448) {
        int r = i >> 7, c = i & 127;
        Wd2p[r * 129 + c] = Wd2[i];
    }
    float b1c[4], b2c[4], w3c[4];
    #pragma unroll
    for (int q = 0; q < 4; ++q) {
        b1c[q] = bd1[lane + 32 * q];
        b2c[q] = bd2[lane + 32 * q];
        w3c[q] = Wd3[lane + 32 * q];
    }
    const float bd3v = bd3[0];
    __syncthreads();

    float wx0[4], wx1[4];
    #pragma unroll
    for (int q = 0; q < 4; ++q) {
        wx0[q] = Wd1p[64 * 129 + lane + 32 * q];
        wx1[q] = Wd1p[65 * 129 + lane + 32 * q];
    }

    const int b = blockIdx.x * GPB + grp;
    if (b < BB) {
        zsh[lane]      = z[b * ZD + lane];
        zsh[lane + 32] = z[b * ZD + lane + 32];
        #pragma unroll
        for (int i = 0; i < 4; ++i) xs[lane + 32 * i] = x_ctx[b * (NCTX * 2) + lane + 32 * i];
        ys[lane] = y_ctx[b * NCTX + lane];      ys[lane + 32] = y_ctx[b * NCTX + lane + 32];
        ms[lane] = mask[b * NCTX + lane];       ms[lane + 32] = mask[b * NCTX + lane + 32];
        __syncwarp();

        // n-invariant layer-1 preactivation per owned column
        float pre1[4] = { b1c[0], b1c[1], b1c[2], b1c[3] };
        #pragma unroll 8
        for (int k = 0; k < ZD; ++k) {
            const float zk = zsh[k];
            #pragma unroll
            for (int q = 0; q < 4; ++q)
                pre1[q] = fmaf(zk, Wd1p[k * 129 + lane + 32 * q], pre1[q]);
        }

        float dps[4] = { 0.0f, 0.0f, 0.0f, 0.0f };
        if (t > 0.0f) {
            #pragma unroll 1
            for (int it = 0; it < NCTX / 8; ++it) {
                const int n0 = it * 8;
                float sd[4][8];
                #pragma unroll
                for (int q = 0; q < 4; ++q) {
                    float hv[8];
                    #pragma unroll
                    for (int n = 0; n < 8; ++n) {
                        const float xa = xs[2 * (n0 + n)], xb = xs[2 * (n0 + n) + 1];
                        const float p = fmaf(xa, wx0[q], fmaf(xb, wx1[q], pre1[q]));
                        const float s = sigf(p);
                        hv[n] = p * s;
                        sd[q][n] = s * (1.0f + p * (1.0f - s));
                    }
                    *(float4*)&h1T[(lane + 32 * q) * 12]     = make_float4(hv[0], hv[1], hv[2], hv[3]);
                    *(float4*)&h1T[(lane + 32 * q) * 12 + 4] = make_float4(hv[4], hv[5], hv[6], hv[7]);
                }
                __syncwarp();                               // A: h1 visible

                u64 acc[4][4];
                #pragma unroll
                for (int q = 0; q < 4; ++q)
                    #pragma unroll
                    for (int p = 0; p < 4; ++p) acc[q][p] = pk2(b2c[q], b2c[q]);
                #pragma unroll 4
                for (int k = 0; k < HD; ++k) {
                    const float4 HA = *(const float4*)&h1T[k * 12];
                    const float4 HB = *(const float4*)&h1T[k * 12 + 4];
                    const u64 h0 = pk2(HA.x, HA.y), h1p = pk2(HA.z, HA.w);
                    const u64 h2p = pk2(HB.x, HB.y), h3p = pk2(HB.z, HB.w);
                    #pragma unroll
                    for (int q = 0; q < 4; ++q) {
                        const float w = Wd2p[k * 129 + lane + 32 * q];
                        const u64 wd = pk2(w, w);
                        fma2(acc[q][0], wd, h0);  fma2(acc[q][1], wd, h1p);
                        fma2(acc[q][2], wd, h2p); fma2(acc[q][3], wd, h3p);
                    }
                }
                float a[4][8], tder[4][8], part[8];
                #pragma unroll
                for (int n = 0; n < 8; ++n) part[n] = 0.0f;
                #pragma unroll
                for (int q = 0; q < 4; ++q) {
                    #pragma unroll
                    for (int p = 0; p < 4; ++p) up2(acc[q][p], a[q][2 * p], a[q][2 * p + 1]);
                    #pragma unroll
                    for (int n = 0; n < 8; ++n) {
                        const float s = sigf(a[q][n]);
                        part[n] = fmaf(a[q][n] * s, w3c[q], part[n]);
                        tder[q][n] = s * (1.0f + a[q][n] * (1.0f - s));
                    }
                }
                #pragma unroll
                for (int off = 16; off; off >>= 1) {
                    #pragma unroll
                    for (int n = 0; n < 8; ++n)
                        part[n] += __shfl_xor_sync(0xffffffffu, part[n], off);
                }
                float e[8];
                #pragma unroll
                for (int n = 0; n < 8; ++n)
                    e[n] = -t * (ys[n0 + n] - (part[n] + bd3v)) * ms[n0 + n];
                __syncwarp();                               // B: fwd reads done
                #pragma unroll
                for (int q = 0; q < 4; ++q) {
                    float dv[8];
                    #pragma unroll
                    for (int n = 0; n < 8; ++n) dv[n] = e[n] * w3c[q] * tder[q][n];
                    *(float4*)&h1T[(lane + 32 * q) * 12]     = make_float4(dv[0], dv[1], dv[2], dv[3]);
                    *(float4*)&h1T[(lane + 32 * q) * 12 + 4] = make_float4(dv[4], dv[5], dv[6], dv[7]);
                }
                __syncwarp();                               // C: dpre2 visible

                u64 bc[4][4];
                #pragma unroll
                for (int q = 0; q < 4; ++q)
                    #pragma unroll
                    for (int p = 0; p < 4; ++p) bc[q][p] = 0ull;
                #pragma unroll 4
                for (int k = 0; k < HD; ++k) {
                    const float4 DA = *(const float4*)&h1T[k * 12];
                    const float4 DB = *(const float4*)&h1T[k * 12 + 4];
                    const u64 d0 = pk2(DA.x, DA.y), d1 = pk2(DA.z, DA.w);
                    const u64 d2 = pk2(DB.x, DB.y), d3 = pk2(DB.z, DB.w);
                    #pragma unroll
                    for (int q = 0; q < 4; ++q) {
                        const float w = Wd2p[(lane + 32 * q) * 129 + k];   // W2^T
                        const u64 wd = pk2(w, w);
                        fma2(bc[q][0], wd, d0); fma2(bc[q][1], wd, d1);
                        fma2(bc[q][2], wd, d2); fma2(bc[q][3], wd, d3);
                    }
                }
                #pragma unroll
                for (int q = 0; q < 4; ++q)
                    #pragma unroll
                    for (int p = 0; p < 4; ++p) {
                        float u, v;
                        up2(bc[q][p], u, v);
                        dps[q] = fmaf(u, sd[q][2 * p], dps[q]);
                        dps[q] = fmaf(v, sd[q][2 * p + 1], dps[q]);
                    }
                __syncwarp();                               // D: h1T reuse next tile
            }
        }
        #pragma unroll
        for (int q = 0; q < 4; ++q) ds[lane + 32 * q] = dps[q];
        __syncwarp();
        {
            float acc0 = 0.0f, acc1 = 0.0f;
            #pragma unroll 8
            for (int j = 0; j < HD; ++j) {
                const float dj = ds[j];
                acc0 = fmaf(dj, Wd1p[lane * 129 + j], acc0);
                acc1 = fmaf(dj, Wd1p[(lane + 32) * 129 + j], acc1);
            }
            float g0 = zsh[lane] + acc0;
            float g1 = zsh[lane + 32] + acc1;
            g0 = fminf(fmaxf(g0, -100.0f), 100.0f);
            g1 = fminf(fmaxf(g1, -100.0f), 100.0f);
            g_grad[b * ZD + lane]      = g0;
            g_grad[b * ZD + lane + 32] = g1;
        }
    }
}

// ---------------- Drift + z update (unchanged) ----------------
__global__ void __launch_bounds__(128, 1) drift_kernel(
    float* __restrict__ z, const float* __restrict__ noise,
    const float* __restrict__ Wf1, const float* __restrict__ bf1,
    const float* __restrict__ Wf2, const float* __restrict__ bf2,
    const float* __restrict__ Wf3, const float* __restrict__ bf3,
    float t)
{
    extern __shared__ float sm[];
    float*  Wf1s = sm;
    float*  Wf2s = Wf1s + 193 * HD;
    float*  Wf3s = Wf2s + HD * HD;
    float4* f1sT = (float4*)(Wf3s + HD * ZD);
    float4* f2sT = f1sT + 128;
    float4* zshT = f2sT + 128;
    float4* rshT = zshT + 64;

    const int tid = threadIdx.x;
    for (int i = tid; i < 193 * HD; i += 128) Wf1s[i] = Wf1[i];
    for (int i = tid; i < HD * HD; i += 128)  Wf2s[i] = Wf2[i];
    for (int i = tid; i < HD * ZD; i += 128)  Wf3s[i] = Wf3[i];
    const float b1 = bf1[tid], b2 = bf2[tid];
    const float bf3v = bf3[tid & 63];
    __syncthreads();
    const float wt = Wf1s[192 * HD + tid];
    const int kk = tid & 63, g2 = tid >> 6;

    for (int b0 = blockIdx.x * 4; b0 < BB; b0 += gridDim.x * 4) {
        float* zf = (float*)zshT;
        float* rf = (float*)rshT;
        #pragma unroll
        for (int i = tid; i < 4 * ZD; i += 128) {
            int q = i >> 6, k = i & 63;
            zf[k * 4 + q] = z[(b0 + q) * ZD + k];
        }
        #pragma unroll
        for (int i = tid; i < 4 * RD; i += 128) {
            int q = i >> 7, k = i & 127;
            rf[k * 4 + q] = g_r[(b0 + q) * RD + k];
        }
        __syncthreads();

        const float pb = fmaf(t, wt, b1);
        float p0 = pb, p1 = pb, p2 = pb, p3 = pb;
        #pragma unroll 8
        for (int k = 0; k < ZD; ++k) {
            const float w = Wf1s[k * HD + tid];
            const float4 v = zshT[k];
            p0 = fmaf(v.x, w, p0); p1 = fmaf(v.y, w, p1);
            p2 = fmaf(v.z, w, p2); p3 = fmaf(v.w, w, p3);
        }
        #pragma unroll 8
        for (int k = 0; k < RD; ++k) {
            const float w = Wf1s[(ZD + k) * HD + tid];
            const float4 v = rshT[k];
            p0 = fmaf(v.x, w, p0); p1 = fmaf(v.y, w, p1);
            p2 = fmaf(v.z, w, p2); p3 = fmaf(v.w, w, p3);
        }
        f1sT[tid] = make_float4(p0 * sigf(p0), p1 * sigf(p1), p2 * sigf(p2), p3 * sigf(p3));
        __syncthreads();

        p0 = b2; p1 = b2; p2 = b2; p3 = b2;
        #pragma unroll 8
        for (int k = 0; k < HD; ++k) {
            const float w = Wf2s[k * HD + tid];
            const float4 v = f1sT[k];
            p0 = fmaf(v.x, w, p0); p1 = fmaf(v.y, w, p1);
            p2 = fmaf(v.z, w, p2); p3 = fmaf(v.w, w, p3);
        }
        f2sT[tid] = make_float4(p0 * sigf(p0), p1 * sigf(p1), p2 * sigf(p2), p3 * sigf(p3));
        __syncthreads();

        float accA = 0.0f, accB = 0.0f;
        #pragma unroll 8
        for (int j = 0; j < HD; ++j) {
            const float w = Wf3s[j * ZD + kk];
            const float4 v = f2sT[j];
            const float vA = g2 ? v.y : v.x;
            const float vB = g2 ? v.w : v.z;
            accA = fmaf(vA, w, accA);
            accB = fmaf(vB, w, accB);
        }
        {
            const int qA = g2, qB = g2 + 2;
            const int bA = b0 + qA, bB = b0 + qB;
            z[bA * ZD + kk] = zf[kk * 4 + qA]
                + (bf3v + accA - g_grad[bA * ZD + kk]) * DT
                + DIFF * noise[bA * ZD + kk];
            z[bB * ZD + kk] = zf[kk * 4 + qB]
                + (bf3v + accB - g_grad[bB * ZD + kk]) * DT
                + DIFF * noise[bB * ZD + kk];
        }
        __syncthreads();
    }
}

// ---------------------------------------------------------------------------
extern "C" void kernel_launch(void* const* d_in, const int* in_sizes, int n_in,
                              void* d_out, int out_size)
{
    const float* x_ctx  = (const float*)d_in[0];
    const float* y_ctx  = (const float*)d_in[1];
    const float* mask   = (const float*)d_in[2];
    const float* z0     = (const float*)d_in[3];
    const float* noises = (const float*)d_in[4];
    const float* We1 = (const float*)d_in[5];  const float* be1 = (const float*)d_in[6];
    const float* We2 = (const float*)d_in[7];  const float* be2 = (const float*)d_in[8];
    const float* We3 = (const float*)d_in[9];  const float* be3 = (const float*)d_in[10];
    const float* Wd1 = (const float*)d_in[11]; const float* bd1 = (const float*)d_in[12];
    const float* Wd2 = (const float*)d_in[13]; const float* bd2 = (const float*)d_in[14];
    const float* Wd3 = (const float*)d_in[15]; const float* bd3 = (const float*)d_in[16];
    const float* Wf1 = (const float*)d_in[17]; const float* bf1 = (const float*)d_in[18];
    const float* Wf2 = (const float*)d_in[19]; const float* bf2 = (const float*)d_in[20];
    const float* Wf3 = (const float*)d_in[21]; const float* bf3 = (const float*)d_in[22];
    float* z = (float*)d_out;

    const size_t smE = (size_t)(512 + 512 + 16384 + 16384 + 128 + 64 + 64) * 4;
    const size_t smG = (size_t)(66 * 129 + 128 * 129 + 2 + GPB * GSZ) * 4;
    const size_t smF = (size_t)(193 * 128 + 128 * 128 + 128 * 64
                                + 512 + 512 + 256 + 512) * 4;

    cudaFuncSetAttribute(encoder_kernel, cudaFuncAttributeMaxDynamicSharedMemorySize, (int)smE);
    cudaFuncSetAttribute(grad_kernel,    cudaFuncAttributeMaxDynamicSharedMemorySize, (int)smG);
    cudaFuncSetAttribute(drift_kernel,   cudaFuncAttributeMaxDynamicSharedMemorySize, (int)smF);

    cudaMemcpyAsync(z, z0, (size_t)BB * ZD * sizeof(float), cudaMemcpyDeviceToDevice);
    encoder_kernel<<<148, 128, smE>>>(x_ctx, y_ctx, mask, We1, be1, We2, be2, We3, be3);

    for (int s = 0; s < NSTEPS; ++s) {
        const float t = (float)s * DT;
        grad_kernel<<<147, 448, smG>>>(z, x_ctx, y_ctx, mask,
                                       Wd1, bd1, Wd2, bd2, Wd3, bd3, t);
        drift_kernel<<<148, 128, smF>>>(z, noises + (size_t)s * BB * ZD,
                                        Wf1, bf1, Wf2, bf2, Wf3, bf3, t);
    }
}